// round 14
// baseline (speedup 1.0000x reference)
#include <cuda_runtime.h>
#include <cstdint>

// Problem constants
#define BB   4
#define SS   1024
#define EE   1024
#define HH   16
#define DD   64
#define PP   1024
#define NSS  2048          // P + S
#define E3   3072          // 3*E

// ---------------------------------------------------------------------------
// Scratch
// ---------------------------------------------------------------------------
__device__ float g_qkv[(size_t)BB * SS * E3];            // [B*S, 3E] (fp32 accum out)
__device__ float g_attn[(size_t)BB * SS * EE];           // [B*S, E]  (tf32-rounded at write)
__device__ float g_x_r[(size_t)BB * SS * EE];            // RNA-rounded x
__device__ float g_wattn_r[(size_t)EE * E3];             // RNA-rounded w_attn
__device__ float g_wproj_r[(size_t)EE * EE];             // RNA-rounded w_proj
__device__ float g_kv_r[(size_t)2 * BB * HH * NSS * DD]; // RNA-rounded present K|V

// ---------------------------------------------------------------------------
// tf32 / cp.async helpers
// ---------------------------------------------------------------------------
__device__ __forceinline__ float to_tf32(float x) {
    float r;
    asm("cvt.rna.tf32.f32 %0, %1;" : "=f"(r) : "f"(x));
    return r;
}

// D += A@B  (m16n8k8, A row-major, B col-major fragments, fp32 accum)
__device__ __forceinline__ void mma8(float* d, const uint32_t* a, const uint32_t* b) {
    asm("mma.sync.aligned.m16n8k8.row.col.f32.tf32.tf32.f32 "
        "{%0,%1,%2,%3}, {%4,%5,%6,%7}, {%8,%9}, {%0,%1,%2,%3};"
        : "+f"(d[0]), "+f"(d[1]), "+f"(d[2]), "+f"(d[3])
        : "r"(a[0]), "r"(a[1]), "r"(a[2]), "r"(a[3]), "r"(b[0]), "r"(b[1]));
}

__device__ __forceinline__ uint32_t fbits(float x) { return __float_as_uint(x); }

__device__ __forceinline__ void cp16(void* sdst, const void* gsrc) {
    uint32_t s = (uint32_t)__cvta_generic_to_shared(sdst);
    asm volatile("cp.async.cg.shared.global [%0], [%1], 16;" :: "r"(s), "l"(gsrc));
}
#define CP_COMMIT() asm volatile("cp.async.commit_group;")
#define CP_WAIT1()  asm volatile("cp.async.wait_group 1;")

// GEMM smem geometry (floats)
#define A_LDA  36
#define B_LDB  136
#define A_SZ   (128 * A_LDA)
#define B_SZ   (32 * B_LDB)
#define STG_SZ (A_SZ + B_SZ)
#define GEMM_SMEM_BYTES (2 * STG_SZ * 4)

// Flash smem geometry (floats)
#define F_LD     72
#define F_KV     (64 * F_LD)
#define F_STG    (2 * F_KV)
#define FLASH_SMEM_BYTES (2 * F_STG * 4)

// ---------------------------------------------------------------------------
// Elementwise RNA-tf32 rounding: dst = RNA(src). float4 per thread.
// ---------------------------------------------------------------------------
__global__ __launch_bounds__(256) void round_tf32_kernel(
    const float* __restrict__ src, float* __restrict__ dst)
{
    int i = blockIdx.x * 256 + threadIdx.x;
    float4 v = reinterpret_cast<const float4*>(src)[i];
    v.x = to_tf32(v.x); v.y = to_tf32(v.y);
    v.z = to_tf32(v.z); v.w = to_tf32(v.w);
    reinterpret_cast<float4*>(dst)[i] = v;
}

// ---------------------------------------------------------------------------
// GEMM + bias: C[M,N] = A[M,K] @ B[K,N] + bias[N]   (tf32 MMA)
// A and B are PRE-ROUNDED to tf32 in gmem -> fragments are raw bits (no cvt).
// Arithmetic identical to the R10 kernel (same RNA rounding, applied earlier).
// ---------------------------------------------------------------------------
template<int N, int K>
__device__ __forceinline__ void mma_gemm_body(
    const float* __restrict__ A, const float* __restrict__ B,
    const float* __restrict__ bias, float* __restrict__ C)
{
    extern __shared__ float sm[];

    const int tid  = threadIdx.x;
    const int lane = tid & 31;
    const int wid  = tid >> 5;
    const int wm   = (wid & 1) * 64;
    const int wn   = (wid >> 1) * 32;
    const int g    = lane >> 2;
    const int tg   = lane & 3;
    const int m0   = blockIdx.y * 128;
    const int n0   = blockIdx.x * 128;

    float acc[4][4][4];
#pragma unroll
    for (int mi = 0; mi < 4; mi++)
#pragma unroll
        for (int ni = 0; ni < 4; ni++)
#pragma unroll
            for (int j = 0; j < 4; j++) acc[mi][ni][j] = 0.f;

    auto copy_tile = [&](int stage, int k0) {
        float* As = sm + stage * STG_SZ;
        float* Bs = As + A_SZ;
#pragma unroll
        for (int it = 0; it < 4; it++) {
            int f   = tid + it * 256;
            int row = f >> 3;
            int kq  = (f & 7) * 4;
            cp16(&As[row * A_LDA + kq], &A[(size_t)(m0 + row) * K + k0 + kq]);
        }
#pragma unroll
        for (int it = 0; it < 4; it++) {
            int f  = tid + it * 256;
            int kr = f >> 5;
            int nc = (f & 31) * 4;
            cp16(&Bs[kr * B_LDB + nc], &B[(size_t)(k0 + kr) * N + n0 + nc]);
        }
    };

    const int nt = K / 32;
    copy_tile(0, 0);
    CP_COMMIT();

    for (int i = 0; i < nt; i++) {
        __syncthreads();                     // all reads of stage (i+1)&1 done
        if (i + 1 < nt) copy_tile((i + 1) & 1, (i + 1) * 32);
        CP_COMMIT();
        CP_WAIT1();                          // own copies for tile i complete
        __syncthreads();                     // ALL threads' copies visible

        const float* As = sm + (i & 1) * STG_SZ;
        const float* Bs = As + A_SZ;

#pragma unroll
        for (int ks = 0; ks < 4; ks++) {
            const int k8 = ks * 8;
            uint32_t af[4][4], bf[4][2];
#pragma unroll
            for (int mi = 0; mi < 4; mi++) {
                const float* ar0 = &As[(wm + mi * 16 + g) * A_LDA + k8 + tg];
                const float* ar1 = ar0 + 8 * A_LDA;
                af[mi][0] = fbits(ar0[0]);
                af[mi][1] = fbits(ar1[0]);
                af[mi][2] = fbits(ar0[4]);
                af[mi][3] = fbits(ar1[4]);
            }
#pragma unroll
            for (int ni = 0; ni < 4; ni++) {
                int bn = wn + ni * 8 + g;
                bf[ni][0] = fbits(Bs[(k8 + tg) * B_LDB + bn]);
                bf[ni][1] = fbits(Bs[(k8 + tg + 4) * B_LDB + bn]);
            }
#pragma unroll
            for (int mi = 0; mi < 4; mi++)
#pragma unroll
                for (int ni = 0; ni < 4; ni++)
                    mma8(acc[mi][ni], af[mi], bf[ni]);
        }
    }

#pragma unroll
    for (int mi = 0; mi < 4; mi++)
#pragma unroll
        for (int ni = 0; ni < 4; ni++) {
            int r = m0 + wm + mi * 16 + g;
            int c = n0 + wn + ni * 8 + tg * 2;
            float b0 = bias[c], b1 = bias[c + 1];
            float2 o0 = make_float2(acc[mi][ni][0] + b0, acc[mi][ni][1] + b1);
            float2 o1 = make_float2(acc[mi][ni][2] + b0, acc[mi][ni][3] + b1);
            *reinterpret_cast<float2*>(&C[(size_t)r * N + c])       = o0;
            *reinterpret_cast<float2*>(&C[(size_t)(r + 8) * N + c]) = o1;
        }
}

__global__ __launch_bounds__(256, 2) void gemm_qkv_kernel(
    const float* __restrict__ b)
{
    mma_gemm_body<E3, EE>(g_x_r, g_wattn_r, b, g_qkv);
}

__global__ __launch_bounds__(256, 2) void gemm_proj_kernel(
    const float* __restrict__ b, float* __restrict__ out)
{
    mma_gemm_body<EE, EE>(g_attn, g_wproj_r, b, out);
}

// ---------------------------------------------------------------------------
// present: exact fp32 concat to output + RNA-rounded copy to g_kv_r for flash.
// ---------------------------------------------------------------------------
__global__ __launch_bounds__(256) void present_kernel(
    const float* __restrict__ past, float* __restrict__ present)
{
    int idx = blockIdx.x * 256 + threadIdx.x;   // float4 index
    int d4 = idx & 15;
    int t  = idx >> 4;
    int n  = t & (NSS - 1);  t >>= 11;
    int h  = t & (HH - 1);   t >>= 4;
    int b  = t & (BB - 1);
    int kv = t >> 2;

    float4 v;
    if (n < PP) {
        size_t src = ((((size_t)kv * BB + b) * HH + h) * PP + n) * 16 + d4;
        v = reinterpret_cast<const float4*>(past)[src];
    } else {
        int s = n - PP;
        v = *reinterpret_cast<const float4*>(
            &g_qkv[((size_t)(b * SS + s)) * E3 + (kv + 1) * EE + h * DD + d4 * 4]);
    }
    reinterpret_cast<float4*>(present)[idx] = v;   // exact (checked output)

    float4 r = make_float4(to_tf32(v.x), to_tf32(v.y), to_tf32(v.z), to_tf32(v.w));
    reinterpret_cast<float4*>(g_kv_r)[idx] = r;    // rounded copy for flash
}

// ---------------------------------------------------------------------------
// Fused flash attention. K/V read from g_kv_r (pre-rounded) -> raw fragments.
// Only P fragments need in-loop cvt (32/tile vs 288 before).
// Epilogue writes RNA-rounded g_attn (proj's pre-rounded A operand).
// ---------------------------------------------------------------------------
__global__ __launch_bounds__(256) void flash_kernel()
{
    extern __shared__ float smf[];   // [2][ K(64x72) | V(64x72) ]; Q prologue uses stage 0

    const int tid  = threadIdx.x;
    const int lane = tid & 31;
    const int wid  = tid >> 5;
    const int wm   = wid * 16;
    const int g    = lane >> 2;
    const int tg   = lane & 3;
    const int qb   = blockIdx.x * 128;
    const int bh   = blockIdx.y;
    const int b    = bh >> 4;
    const int h    = bh & 15;

    const float* Q  = g_qkv + ((size_t)(b * SS + qb)) * E3 + h * DD;
    const float* Kp = g_kv_r + (size_t)bh * NSS * DD;
    const float* Vp = g_kv_r + ((size_t)BB * HH + bh) * NSS * DD;

    // ---- Prologue: stage Q tile (tf32-rounded once here), build A-fragments ----
#pragma unroll
    for (int it = 0; it < 8; it++) {
        int f   = tid + it * 256;
        int row = f >> 4;
        int c4  = (f & 15) * 4;
        float4 v = *reinterpret_cast<const float4*>(&Q[(size_t)row * E3 + c4]);
        float* qrow = &smf[row * F_LD];
        qrow[c4 + 0] = to_tf32(v.x); qrow[c4 + 1] = to_tf32(v.y);
        qrow[c4 + 2] = to_tf32(v.z); qrow[c4 + 3] = to_tf32(v.w);
    }
    __syncthreads();

    uint32_t qf[8][4];
#pragma unroll
    for (int d8 = 0; d8 < 8; d8++) {
        qf[d8][0] = fbits(smf[(wm + g    ) * F_LD + d8 * 8 + tg    ]);
        qf[d8][1] = fbits(smf[(wm + g + 8) * F_LD + d8 * 8 + tg    ]);
        qf[d8][2] = fbits(smf[(wm + g    ) * F_LD + d8 * 8 + tg + 4]);
        qf[d8][3] = fbits(smf[(wm + g + 8) * F_LD + d8 * 8 + tg + 4]);
    }
    __syncthreads();   // stage 0 free for K/V

    auto copy_kv = [&](int stage, int kb) {
        float* Ks = smf + stage * F_STG;
        float* Vs = Ks + F_KV;
#pragma unroll
        for (int it = 0; it < 4; it++) {
            int f   = tid + it * 256;
            int row = f >> 4;
            int c4  = (f & 15) * 4;
            cp16(&Ks[row * F_LD + c4], &Kp[(size_t)(kb + row) * DD + c4]);
        }
#pragma unroll
        for (int it = 0; it < 4; it++) {
            int f   = tid + it * 256;
            int row = f >> 4;
            int c4  = (f & 15) * 4;
            cp16(&Vs[row * F_LD + c4], &Vp[(size_t)(kb + row) * DD + c4]);
        }
    };

    // ---- Online softmax state + O accumulator ----
    float m_lo = -1e30f, m_hi = -1e30f, l_lo = 0.f, l_hi = 0.f;
    float o[8][4];
#pragma unroll
    for (int nd = 0; nd < 8; nd++)
#pragma unroll
        for (int j = 0; j < 4; j++) o[nd][j] = 0.f;

    const int q_lo = qb + wm + g;
    const int nt   = (PP + qb) / 64 + 2;
    const int diag0 = (PP + qb) / 64;

    copy_kv(0, 0);
    CP_COMMIT();

    for (int t = 0; t < nt; t++) {
        const int kb = t * 64;
        __syncthreads();
        if (t + 1 < nt) copy_kv((t + 1) & 1, (t + 1) * 64);
        CP_COMMIT();
        CP_WAIT1();
        __syncthreads();

        const float* Ks = smf + (t & 1) * F_STG;
        const float* Vs = Ks + F_KV;

        // ---- S = Q @ K^T  (raw fragments, K pre-rounded) ----
        float s[8][4];
#pragma unroll
        for (int ni = 0; ni < 8; ni++) {
            s[ni][0] = 0.f; s[ni][1] = 0.f; s[ni][2] = 0.f; s[ni][3] = 0.f;
            const float* krow = &Ks[(ni * 8 + g) * F_LD];
#pragma unroll
            for (int d8 = 0; d8 < 8; d8++) {
                uint32_t bf[2];
                bf[0] = fbits(krow[d8 * 8 + tg    ]);
                bf[1] = fbits(krow[d8 * 8 + tg + 4]);
                mma8(s[ni], qf[d8], bf);
            }
        }

        // scale + causal mask (exactly -10000 like the reference)
        const bool diag = (t >= diag0);
#pragma unroll
        for (int ni = 0; ni < 8; ni++) {
            s[ni][0] *= 0.125f; s[ni][1] *= 0.125f;
            s[ni][2] *= 0.125f; s[ni][3] *= 0.125f;
            if (diag) {
                int kc = kb + ni * 8 + tg * 2;
                if (kc     > PP + q_lo)     s[ni][0] = -10000.f;
                if (kc + 1 > PP + q_lo)     s[ni][1] = -10000.f;
                if (kc     > PP + q_lo + 8) s[ni][2] = -10000.f;
                if (kc + 1 > PP + q_lo + 8) s[ni][3] = -10000.f;
            }
        }

        // ---- row max ----
        float tl = -1e30f, th = -1e30f;
#pragma unroll
        for (int ni = 0; ni < 8; ni++) {
            tl = fmaxf(tl, fmaxf(s[ni][0], s[ni][1]));
            th = fmaxf(th, fmaxf(s[ni][2], s[ni][3]));
        }
        tl = fmaxf(tl, __shfl_xor_sync(0xffffffffu, tl, 1));
        tl = fmaxf(tl, __shfl_xor_sync(0xffffffffu, tl, 2));
        th = fmaxf(th, __shfl_xor_sync(0xffffffffu, th, 1));
        th = fmaxf(th, __shfl_xor_sync(0xffffffffu, th, 2));

        float mn_lo = fmaxf(m_lo, tl);
        float mn_hi = fmaxf(m_hi, th);
        float al = __expf(m_lo - mn_lo);
        float ah = __expf(m_hi - mn_hi);

        // ---- exp + row sum ----
        float sl = 0.f, sh = 0.f;
#pragma unroll
        for (int ni = 0; ni < 8; ni++) {
            s[ni][0] = __expf(s[ni][0] - mn_lo);
            s[ni][1] = __expf(s[ni][1] - mn_lo);
            s[ni][2] = __expf(s[ni][2] - mn_hi);
            s[ni][3] = __expf(s[ni][3] - mn_hi);
            sl += s[ni][0] + s[ni][1];
            sh += s[ni][2] + s[ni][3];
        }
        sl += __shfl_xor_sync(0xffffffffu, sl, 1);
        sl += __shfl_xor_sync(0xffffffffu, sl, 2);
        sh += __shfl_xor_sync(0xffffffffu, sh, 1);
        sh += __shfl_xor_sync(0xffffffffu, sh, 2);

        l_lo = l_lo * al + sl;
        l_hi = l_hi * ah + sh;
        m_lo = mn_lo;
        m_hi = mn_hi;

        // ---- rescale O ----
#pragma unroll
        for (int nd = 0; nd < 8; nd++) {
            o[nd][0] *= al; o[nd][1] *= al;
            o[nd][2] *= ah; o[nd][3] *= ah;
        }

        // ---- PV: O += P @ V ----
        const int src0 = (lane & ~3) | (tg >> 1);
        const int src2 = src0 + 2;
        const bool odd = tg & 1;
#pragma unroll
        for (int j = 0; j < 8; j++) {
            float e0 = __shfl_sync(0xffffffffu, s[j][0], src0);
            float e1 = __shfl_sync(0xffffffffu, s[j][1], src0);
            float e2 = __shfl_sync(0xffffffffu, s[j][2], src0);
            float e3 = __shfl_sync(0xffffffffu, s[j][3], src0);
            float f0 = __shfl_sync(0xffffffffu, s[j][0], src2);
            float f1 = __shfl_sync(0xffffffffu, s[j][1], src2);
            float f2 = __shfl_sync(0xffffffffu, s[j][2], src2);
            float f3 = __shfl_sync(0xffffffffu, s[j][3], src2);
            uint32_t pa[4];
            pa[0] = fbits(to_tf32(odd ? e1 : e0));
            pa[1] = fbits(to_tf32(odd ? e3 : e2));
            pa[2] = fbits(to_tf32(odd ? f1 : f0));
            pa[3] = fbits(to_tf32(odd ? f3 : f2));
            const float* vr0 = &Vs[(j * 8 + tg    ) * F_LD];
            const float* vr1 = &Vs[(j * 8 + tg + 4) * F_LD];
#pragma unroll
            for (int nd = 0; nd < 8; nd++) {
                uint32_t bf[2];
                bf[0] = fbits(vr0[nd * 8 + g]);
                bf[1] = fbits(vr1[nd * 8 + g]);
                mma8(o[nd], pa, bf);
            }
        }
    }

    // ---- Epilogue: normalize, RNA-round, write merged-head attn ----
    float il_lo = 1.f / l_lo;
    float il_hi = 1.f / l_hi;
#pragma unroll
    for (int nd = 0; nd < 8; nd++) {
        int dc = nd * 8 + tg * 2;
        size_t off = ((size_t)(b * SS + q_lo)) * EE + h * DD + dc;
        *reinterpret_cast<float2*>(&g_attn[off]) =
            make_float2(to_tf32(o[nd][0] * il_lo), to_tf32(o[nd][1] * il_lo));
        *reinterpret_cast<float2*>(&g_attn[off + (size_t)8 * EE]) =
            make_float2(to_tf32(o[nd][2] * il_hi), to_tf32(o[nd][3] * il_hi));
    }
}

// ---------------------------------------------------------------------------
// Launch. Output layout: [ out (B*S*E) | present (2*B*H*NS*D) ]
// ---------------------------------------------------------------------------
extern "C" void kernel_launch(void* const* d_in, const int* in_sizes, int n_in,
                              void* d_out, int out_size)
{
    (void)in_sizes; (void)n_in; (void)out_size;
    const float* x      = (const float*)d_in[0];
    const float* past   = (const float*)d_in[1];
    const float* w_attn = (const float*)d_in[2];
    const float* b_attn = (const float*)d_in[3];
    const float* w_proj = (const float*)d_in[4];
    const float* b_proj = (const float*)d_in[5];

    float* out      = (float*)d_out;
    float* present  = out + (size_t)BB * SS * EE;

    cudaFuncSetAttribute(gemm_qkv_kernel,
                         cudaFuncAttributeMaxDynamicSharedMemorySize, GEMM_SMEM_BYTES);
    cudaFuncSetAttribute(gemm_proj_kernel,
                         cudaFuncAttributeMaxDynamicSharedMemorySize, GEMM_SMEM_BYTES);
    cudaFuncSetAttribute(flash_kernel,
                         cudaFuncAttributeMaxDynamicSharedMemorySize, FLASH_SMEM_BYTES);

    // 0) Pre-round GEMM inputs to tf32 (RNA) once, in gmem.
    float* gx; cudaGetSymbolAddress((void**)&gx, g_x_r);
    float* gw; cudaGetSymbolAddress((void**)&gw, g_wattn_r);
    float* gp; cudaGetSymbolAddress((void**)&gp, g_wproj_r);
    round_tf32_kernel<<<(BB * SS * EE) / 1024, 256>>>(x, gx);
    round_tf32_kernel<<<(EE * E3) / 1024, 256>>>(w_attn, gw);
    round_tf32_kernel<<<(EE * EE) / 1024, 256>>>(w_proj, gp);

    // 1) QKV = x @ w_attn + b_attn
    gemm_qkv_kernel<<<dim3(E3 / 128, (BB * SS) / 128), 256, GEMM_SMEM_BYTES>>>(b_attn);

    // 2) present = concat(past, new K/V); also writes rounded copy for flash
    {
        int n4 = 2 * BB * HH * NSS * (DD / 4);
        present_kernel<<<n4 / 256, 256>>>(past, present);
    }

    // 3) fused scores + softmax + PV
    flash_kernel<<<dim3(SS / 128, BB * HH), 256, FLASH_SMEM_BYTES>>>();

    // 4) out = attn @ w_proj + b_proj
    gemm_proj_kernel<<<dim3(EE / 128, (BB * SS) / 128), 256, GEMM_SMEM_BYTES>>>(b_proj, out);
}